// round 3
// baseline (speedup 1.0000x reference)
#include <cuda_runtime.h>

// ---------------------------------------------------------------------------
// FeatExtractor: conv1(12->64,3x3,SAME)+relu+maxpool2x2 -> conv2(64->128,3x3)
//                +relu -> per-roi-id segment max over 64x64 positions.
// Inputs (metadata order):
//   0: images  (32,4,3,128,128) f32   1: rois (32,128,128) i32
//   2: conv1_w (64,12,3,3) f32        3: conv1_b (64) f32
//   4: conv2_w (128,64,3,3) f32       5: conv2_b (128) f32
// Output: (32, 32, 128) f32
// ---------------------------------------------------------------------------

#define NB 32

// Scratch (device globals: allocation-free rule)
__device__ float g_w1t[12 * 9 * 64];      // [ci*9+tap][co]  (includes 1/255)
__device__ float g_w2t[64 * 9 * 128];     // [ci*9+tap][co]
__device__ float g_x1[(size_t)NB * 64 * 64 * 64];  // pooled conv1 output, 32 MB

// ---------------------------------------------------------------------------
// Weight transpose + scale fold
// ---------------------------------------------------------------------------
__global__ void prep_weights_kernel(const float* __restrict__ w1,
                                    const float* __restrict__ w2) {
    int t = blockIdx.x * 256 + threadIdx.x;
    if (t < 6912) {
        int co = t & 63;
        int row = t >> 6;                 // ci*9+tap, 0..107
        g_w1t[t] = w1[co * 108 + row] * (1.0f / 255.0f);
    }
    int u = t - 6912;
    if (u >= 0 && u < 73728) {
        int co = u & 127;
        int row = u >> 7;                 // ci*9+tap, 0..575
        g_w2t[u] = w2[co * 576 + row];
    }
}

// ---------------------------------------------------------------------------
// Kernel A: conv1 + bias + relu + 2x2 maxpool
// Block: pooled tile 8x16 (conv region 16x32, halo 18x34), 512 threads.
// Thread: 1 pooled pixel (4 conv px) x 16 output channels.
// Grid: (4, 8, 32)
// ---------------------------------------------------------------------------
__global__ void __launch_bounds__(512, 1)
conv1_pool_kernel(const float* __restrict__ img, const float* __restrict__ b1) {
    extern __shared__ __align__(16) float sm[];
    float* s_in = sm;                       // [12][18][34] = 7344
    float* s_w  = sm + 7344;                // [12*9][64]   = 6912
    float* s_b  = sm + 7344 + 6912;         // 64

    const int b   = blockIdx.z;
    const int ty0 = blockIdx.y * 8;         // pooled tile origin
    const int tx0 = blockIdx.x * 16;
    const int hy0 = ty0 * 2 - 1;            // input halo origin
    const int hx0 = tx0 * 2 - 1;
    const int tid = threadIdx.x;

    for (int e = tid; e < 6912; e += 512) s_w[e] = g_w1t[e];
    if (tid < 64) s_b[tid] = b1[tid];

    const float* imgb = img + b * (12 * 128 * 128);
    for (int e = tid; e < 12 * 18 * 34; e += 512) {
        int ci  = e / (18 * 34);
        int rem = e - ci * (18 * 34);
        int r = rem / 34, c = rem - r * 34;
        int iy = hy0 + r, ix = hx0 + c;
        float v = 0.0f;
        if ((unsigned)iy < 128u && (unsigned)ix < 128u)
            v = imgb[ci * 16384 + iy * 128 + ix];
        s_in[e] = v;
    }
    __syncthreads();

    const int cg = tid & 3;                 // 4 groups of 16 co
    const int pp = tid >> 2;                // pooled pixel 0..127
    const int py = pp >> 4, px = pp & 15;
    const int co0 = cg * 16;

    float acc[4][16];
#pragma unroll
    for (int d = 0; d < 4; d++)
#pragma unroll
        for (int k = 0; k < 16; k++) acc[d][k] = 0.0f;

    for (int ci = 0; ci < 12; ci++) {
        const float* sic = s_in + ci * (18 * 34) + (2 * py) * 34 + 2 * px;
        const float* swc = s_w + ci * 576 + co0;
#pragma unroll
        for (int t = 0; t < 9; t++) {
            const int ky = t / 3, kx = t - 3 * (t / 3);
            const float4* wp = reinterpret_cast<const float4*>(swc + t * 64);
            float4 q0 = wp[0], q1 = wp[1], q2 = wp[2], q3 = wp[3];
            float wv[16] = {q0.x, q0.y, q0.z, q0.w, q1.x, q1.y, q1.z, q1.w,
                            q2.x, q2.y, q2.z, q2.w, q3.x, q3.y, q3.z, q3.w};
#pragma unroll
            for (int d = 0; d < 4; d++) {
                const int dy = d >> 1, dx = d & 1;
                float inv = sic[(dy + ky) * 34 + (dx + kx)];
#pragma unroll
                for (int k = 0; k < 16; k++)
                    acc[d][k] = fmaf(inv, wv[k], acc[d][k]);
            }
        }
    }

    // bias + relu + maxpool, store pooled
    float* x1b = g_x1 + (size_t)b * (64 * 4096);
    const int pidx = (ty0 + py) * 64 + (tx0 + px);
#pragma unroll
    for (int k = 0; k < 16; k++) {
        float m = fmaxf(fmaxf(acc[0][k], acc[1][k]),
                        fmaxf(acc[2][k], acc[3][k]));
        float v = fmaxf(m + s_b[co0 + k], 0.0f);
        x1b[(co0 + k) * 4096 + pidx] = v;
    }
}

// ---------------------------------------------------------------------------
// Kernel B: conv2 + bias + relu + per-roi segment max
// Block: output tile 8x16 of 64x64 (halo 10x18), 256 threads.
// Thread: 4 horizontal pixels x 16 output channels.
// Grid: (4, 8, 32)
// ---------------------------------------------------------------------------
__global__ void __launch_bounds__(256, 2)
conv2_seg_kernel(const float* __restrict__ b2, const int* __restrict__ rois,
                 float* __restrict__ out) {
    extern __shared__ __align__(16) float sm[];
    float* s_in  = sm;                         // [64][10][18] = 11520
    float* s_w   = sm + 11520;                 // [8*9][128]   = 9216
    float* s_b   = sm + 11520 + 9216;          // 128
    int*   s_seg = (int*)(sm + 11520 + 9216 + 128);  // [32][128] = 4096
    int*   s_id  = s_seg + 4096;               // [8][16] = 128

    const int b  = blockIdx.z;
    const int y0 = blockIdx.y * 8;
    const int x0 = blockIdx.x * 16;
    const int tid = threadIdx.x;

    for (int e = tid; e < 4096; e += 256) s_seg[e] = 0;
    if (tid < 128) s_b[tid] = b2[tid];
    if (tid < 128) {
        int r = tid >> 4, c = tid & 15;
        s_id[tid] = rois[b * 16384 + (2 * (y0 + r)) * 128 + 2 * (x0 + c)];
    }

    const float* x1b = g_x1 + (size_t)b * (64 * 4096);
    for (int e = tid; e < 11520; e += 256) {
        int ci  = e / 180;
        int rem = e - ci * 180;
        int r = rem / 18, c = rem - r * 18;
        int iy = y0 - 1 + r, ix = x0 - 1 + c;
        float v = 0.0f;
        if ((unsigned)iy < 64u && (unsigned)ix < 64u)
            v = x1b[ci * 4096 + iy * 64 + ix];
        s_in[e] = v;
    }

    const int cg = tid & 7;                 // 8 groups of 16 co
    const int pg = tid >> 3;                // 32 pixel groups of 4
    const int r  = pg >> 2;                 // row 0..7
    const int xq = (pg & 3) * 4;            // col base 0,4,8,12
    const int co0 = cg * 16;

    float acc[4][16];
#pragma unroll
    for (int d = 0; d < 4; d++)
#pragma unroll
        for (int k = 0; k < 16; k++) acc[d][k] = 0.0f;

    for (int chunk = 0; chunk < 8; chunk++) {
        __syncthreads();   // (chunk 0: covers s_in/s_seg/s_id; later: s_w reuse)
        const float* wsrc = g_w2t + chunk * 9216;
        for (int e = tid; e < 9216; e += 256) s_w[e] = wsrc[e];
        __syncthreads();

        for (int cil = 0; cil < 8; cil++) {
            const float* sic = s_in + (chunk * 8 + cil) * 180 + r * 18 + xq;
            const float* swc = s_w + cil * (9 * 128) + co0;
#pragma unroll
            for (int t = 0; t < 9; t++) {
                const int ky = t / 3, kx = t - 3 * (t / 3);
                const float4* wp = reinterpret_cast<const float4*>(swc + t * 128);
                float4 q0 = wp[0], q1 = wp[1], q2 = wp[2], q3 = wp[3];
                float wv[16] = {q0.x, q0.y, q0.z, q0.w, q1.x, q1.y, q1.z, q1.w,
                                q2.x, q2.y, q2.z, q2.w, q3.x, q3.y, q3.z, q3.w};
#pragma unroll
                for (int d = 0; d < 4; d++) {
                    float inv = sic[ky * 18 + (d + kx)];
#pragma unroll
                    for (int k = 0; k < 16; k++)
                        acc[d][k] = fmaf(inv, wv[k], acc[d][k]);
                }
            }
        }
    }

    // bias + relu + smem segment max (float-as-int atomicMax valid: v >= 0)
#pragma unroll
    for (int d = 0; d < 4; d++) {
        int id = s_id[r * 16 + xq + d];
        int base = id * 128 + co0;
#pragma unroll
        for (int k = 0; k < 16; k++) {
            float v = acc[d][k] + s_b[co0 + k];
            if (v > 0.0f) atomicMax(&s_seg[base + k], __float_as_int(v));
        }
    }
    __syncthreads();

    // merge block-local segment table into global output
    float* outb = out + b * (32 * 128);
    for (int e = tid; e < 4096; e += 256) {
        int v = s_seg[e];
        if (v != 0) atomicMax((int*)&outb[e], v);
    }
}

// ---------------------------------------------------------------------------
extern "C" void kernel_launch(void* const* d_in, const int* in_sizes, int n_in,
                              void* d_out, int out_size) {
    const float* img  = (const float*)d_in[0];
    const int*   rois = (const int*)d_in[1];
    const float* w1   = (const float*)d_in[2];
    const float* b1   = (const float*)d_in[3];
    const float* w2   = (const float*)d_in[4];
    const float* b2   = (const float*)d_in[5];
    float* out = (float*)d_out;

    const int smemA = (7344 + 6912 + 64) * 4;                  // 57280 B
    const int smemB = (11520 + 9216 + 128 + 4096 + 128) * 4;   // 100352 B
    cudaFuncSetAttribute(conv1_pool_kernel,
                         cudaFuncAttributeMaxDynamicSharedMemorySize, smemA);
    cudaFuncSetAttribute(conv2_seg_kernel,
                         cudaFuncAttributeMaxDynamicSharedMemorySize, smemB);

    cudaMemsetAsync(d_out, 0, (size_t)out_size * sizeof(float));

    prep_weights_kernel<<<(6912 + 73728 + 255) / 256, 256>>>(w1, w2);

    dim3 gridA(4, 8, NB);
    conv1_pool_kernel<<<gridA, 512, smemA>>>(img, b1);

    dim3 gridB(4, 8, NB);
    conv2_seg_kernel<<<gridB, 256, smemB>>>(b2, rois, out);
}

// round 4
// speedup vs baseline: 1.0015x; 1.0015x over previous
#include <cuda_runtime.h>

// ---------------------------------------------------------------------------
// FeatExtractor: conv1(12->64,3x3,SAME)+relu+maxpool2x2 -> conv2(64->128,3x3)
//                +relu -> per-roi-id segment max over 64x64 positions.
// Inputs (metadata order):
//   0: images  (32,4,3,128,128) f32   1: rois (32,128,128) i32
//   2: conv1_w (64,12,3,3) f32        3: conv1_b (64) f32
//   4: conv2_w (128,64,3,3) f32       5: conv2_b (128) f32
// Output: (32, 32, 128) f32
// ---------------------------------------------------------------------------

#define NB 32

// Scratch (device globals: allocation-free rule)
__device__ float g_w1t[12 * 9 * 64];      // [ci*9+tap][co]  (includes 1/255)
__device__ float g_w2t[64 * 9 * 128];     // [ci*9+tap][co]
__device__ float g_x1[(size_t)NB * 64 * 64 * 64];  // pooled conv1 output, 32 MB

// ---------------------------------------------------------------------------
// Weight transpose + scale fold
// ---------------------------------------------------------------------------
__global__ void prep_weights_kernel(const float* __restrict__ w1,
                                    const float* __restrict__ w2) {
    int t = blockIdx.x * 256 + threadIdx.x;
    if (t < 6912) {
        int co = t & 63;
        int row = t >> 6;                 // ci*9+tap, 0..107
        g_w1t[t] = w1[co * 108 + row] * (1.0f / 255.0f);
    }
    int u = t - 6912;
    if (u >= 0 && u < 73728) {
        int co = u & 127;
        int row = u >> 7;                 // ci*9+tap, 0..575
        g_w2t[u] = w2[co * 576 + row];
    }
}

// ---------------------------------------------------------------------------
// Kernel A: conv1 + bias + relu + 2x2 maxpool
// Block: pooled tile 8x16 (conv region 16x32, halo 18x34), 512 threads.
// Thread: 1 pooled pixel (4 conv px) x 16 output channels.
// Grid: (4, 8, 32)
// ---------------------------------------------------------------------------
__global__ void __launch_bounds__(512, 1)
conv1_pool_kernel(const float* __restrict__ img, const float* __restrict__ b1) {
    extern __shared__ __align__(16) float sm[];
    float* s_in = sm;                       // [12][18][34] = 7344
    float* s_w  = sm + 7344;                // [12*9][64]   = 6912
    float* s_b  = sm + 7344 + 6912;         // 64

    const int b   = blockIdx.z;
    const int ty0 = blockIdx.y * 8;         // pooled tile origin
    const int tx0 = blockIdx.x * 16;
    const int hy0 = ty0 * 2 - 1;            // input halo origin
    const int hx0 = tx0 * 2 - 1;
    const int tid = threadIdx.x;

    for (int e = tid; e < 6912; e += 512) s_w[e] = g_w1t[e];
    if (tid < 64) s_b[tid] = b1[tid];

    const float* imgb = img + b * (12 * 128 * 128);
    for (int e = tid; e < 12 * 18 * 34; e += 512) {
        int ci  = e / (18 * 34);
        int rem = e - ci * (18 * 34);
        int r = rem / 34, c = rem - r * 34;
        int iy = hy0 + r, ix = hx0 + c;
        float v = 0.0f;
        if ((unsigned)iy < 128u && (unsigned)ix < 128u)
            v = imgb[ci * 16384 + iy * 128 + ix];
        s_in[e] = v;
    }
    __syncthreads();

    const int cg = tid & 3;                 // 4 groups of 16 co
    const int pp = tid >> 2;                // pooled pixel 0..127
    const int py = pp >> 4, px = pp & 15;
    const int co0 = cg * 16;

    float acc[4][16];
#pragma unroll
    for (int d = 0; d < 4; d++)
#pragma unroll
        for (int k = 0; k < 16; k++) acc[d][k] = 0.0f;

    for (int ci = 0; ci < 12; ci++) {
        const float* sic = s_in + ci * (18 * 34) + (2 * py) * 34 + 2 * px;
        const float* swc = s_w + ci * 576 + co0;
#pragma unroll
        for (int t = 0; t < 9; t++) {
            const int ky = t / 3, kx = t - 3 * (t / 3);
            const float4* wp = reinterpret_cast<const float4*>(swc + t * 64);
            float4 q0 = wp[0], q1 = wp[1], q2 = wp[2], q3 = wp[3];
            float wv[16] = {q0.x, q0.y, q0.z, q0.w, q1.x, q1.y, q1.z, q1.w,
                            q2.x, q2.y, q2.z, q2.w, q3.x, q3.y, q3.z, q3.w};
#pragma unroll
            for (int d = 0; d < 4; d++) {
                const int dy = d >> 1, dx = d & 1;
                float inv = sic[(dy + ky) * 34 + (dx + kx)];
#pragma unroll
                for (int k = 0; k < 16; k++)
                    acc[d][k] = fmaf(inv, wv[k], acc[d][k]);
            }
        }
    }

    // bias + relu + maxpool, store pooled
    float* x1b = g_x1 + (size_t)b * (64 * 4096);
    const int pidx = (ty0 + py) * 64 + (tx0 + px);
#pragma unroll
    for (int k = 0; k < 16; k++) {
        float m = fmaxf(fmaxf(acc[0][k], acc[1][k]),
                        fmaxf(acc[2][k], acc[3][k]));
        float v = fmaxf(m + s_b[co0 + k], 0.0f);
        x1b[(co0 + k) * 4096 + pidx] = v;
    }
}

// ---------------------------------------------------------------------------
// Kernel B: conv2 + bias + relu + per-roi segment max
// Block: output tile 8x16 of 64x64 (halo 10x18), 256 threads.
// Thread: 4 horizontal pixels x 16 output channels.
// Grid: (4, 8, 32)
// ---------------------------------------------------------------------------
__global__ void __launch_bounds__(256, 2)
conv2_seg_kernel(const float* __restrict__ b2, const int* __restrict__ rois,
                 float* __restrict__ out) {
    extern __shared__ __align__(16) float sm[];
    float* s_in  = sm;                         // [64][10][18] = 11520
    float* s_w   = sm + 11520;                 // [8*9][128]   = 9216
    float* s_b   = sm + 11520 + 9216;          // 128
    int*   s_seg = (int*)(sm + 11520 + 9216 + 128);  // [32][128] = 4096
    int*   s_id  = s_seg + 4096;               // [8][16] = 128

    const int b  = blockIdx.z;
    const int y0 = blockIdx.y * 8;
    const int x0 = blockIdx.x * 16;
    const int tid = threadIdx.x;

    for (int e = tid; e < 4096; e += 256) s_seg[e] = 0;
    if (tid < 128) s_b[tid] = b2[tid];
    if (tid < 128) {
        int r = tid >> 4, c = tid & 15;
        s_id[tid] = rois[b * 16384 + (2 * (y0 + r)) * 128 + 2 * (x0 + c)];
    }

    const float* x1b = g_x1 + (size_t)b * (64 * 4096);
    for (int e = tid; e < 11520; e += 256) {
        int ci  = e / 180;
        int rem = e - ci * 180;
        int r = rem / 18, c = rem - r * 18;
        int iy = y0 - 1 + r, ix = x0 - 1 + c;
        float v = 0.0f;
        if ((unsigned)iy < 64u && (unsigned)ix < 64u)
            v = x1b[ci * 4096 + iy * 64 + ix];
        s_in[e] = v;
    }

    const int cg = tid & 7;                 // 8 groups of 16 co
    const int pg = tid >> 3;                // 32 pixel groups of 4
    const int r  = pg >> 2;                 // row 0..7
    const int xq = (pg & 3) * 4;            // col base 0,4,8,12
    const int co0 = cg * 16;

    float acc[4][16];
#pragma unroll
    for (int d = 0; d < 4; d++)
#pragma unroll
        for (int k = 0; k < 16; k++) acc[d][k] = 0.0f;

    for (int chunk = 0; chunk < 8; chunk++) {
        __syncthreads();   // (chunk 0: covers s_in/s_seg/s_id; later: s_w reuse)
        const float* wsrc = g_w2t + chunk * 9216;
        for (int e = tid; e < 9216; e += 256) s_w[e] = wsrc[e];
        __syncthreads();

        for (int cil = 0; cil < 8; cil++) {
            const float* sic = s_in + (chunk * 8 + cil) * 180 + r * 18 + xq;
            const float* swc = s_w + cil * (9 * 128) + co0;
#pragma unroll
            for (int t = 0; t < 9; t++) {
                const int ky = t / 3, kx = t - 3 * (t / 3);
                const float4* wp = reinterpret_cast<const float4*>(swc + t * 128);
                float4 q0 = wp[0], q1 = wp[1], q2 = wp[2], q3 = wp[3];
                float wv[16] = {q0.x, q0.y, q0.z, q0.w, q1.x, q1.y, q1.z, q1.w,
                                q2.x, q2.y, q2.z, q2.w, q3.x, q3.y, q3.z, q3.w};
#pragma unroll
                for (int d = 0; d < 4; d++) {
                    float inv = sic[ky * 18 + (d + kx)];
#pragma unroll
                    for (int k = 0; k < 16; k++)
                        acc[d][k] = fmaf(inv, wv[k], acc[d][k]);
                }
            }
        }
    }

    // bias + relu + smem segment max (float-as-int atomicMax valid: v >= 0)
#pragma unroll
    for (int d = 0; d < 4; d++) {
        int id = s_id[r * 16 + xq + d];
        int base = id * 128 + co0;
#pragma unroll
        for (int k = 0; k < 16; k++) {
            float v = acc[d][k] + s_b[co0 + k];
            if (v > 0.0f) atomicMax(&s_seg[base + k], __float_as_int(v));
        }
    }
    __syncthreads();

    // merge block-local segment table into global output
    float* outb = out + b * (32 * 128);
    for (int e = tid; e < 4096; e += 256) {
        int v = s_seg[e];
        if (v != 0) atomicMax((int*)&outb[e], v);
    }
}

// ---------------------------------------------------------------------------
extern "C" void kernel_launch(void* const* d_in, const int* in_sizes, int n_in,
                              void* d_out, int out_size) {
    const float* img  = (const float*)d_in[0];
    const int*   rois = (const int*)d_in[1];
    const float* w1   = (const float*)d_in[2];
    const float* b1   = (const float*)d_in[3];
    const float* w2   = (const float*)d_in[4];
    const float* b2   = (const float*)d_in[5];
    float* out = (float*)d_out;

    const int smemA = (7344 + 6912 + 64) * 4;                  // 57280 B
    const int smemB = (11520 + 9216 + 128 + 4096 + 128) * 4;   // 100352 B
    cudaFuncSetAttribute(conv1_pool_kernel,
                         cudaFuncAttributeMaxDynamicSharedMemorySize, smemA);
    cudaFuncSetAttribute(conv2_seg_kernel,
                         cudaFuncAttributeMaxDynamicSharedMemorySize, smemB);

    cudaMemsetAsync(d_out, 0, (size_t)out_size * sizeof(float));

    prep_weights_kernel<<<(6912 + 73728 + 255) / 256, 256>>>(w1, w2);

    dim3 gridA(4, 8, NB);
    conv1_pool_kernel<<<gridA, 512, smemA>>>(img, b1);

    dim3 gridB(4, 8, NB);
    conv2_seg_kernel<<<gridB, 256, smemB>>>(b2, rois, out);
}